// round 17
// baseline (speedup 1.0000x reference)
#include <cuda_runtime.h>
#include <cstdint>

// Problem constants (fixed shapes from setup_inputs)
#define BB 64
#define CC 3
#define HH 224
#define WW 224
#define CW (CC * WW)          // 672
#define NN 224                // Gram size
#define NB 112                // blocks of 2 columns
#define TAIL 45               // 224 - int(0.8*224)
#define NSWEEP 8              // cap; early-exit may trigger sooner
#define THR 1e-9f             // relative skip threshold (cos^2)

// Scratch (device globals: allocation-free per harness rules)
__device__ float g_A[BB * HH * CW];     // masked, scaled input  [b][h][cw]
__device__ float g_G[BB * NN * NN];     // Gram A A^T per image
__device__ float g_Ut[BB * TAIL * NN];  // tail eigenvectors, row t = u_t^T
__device__ int   g_cnt[BB];             // observed-entry counts

// ---------------------------------------------------------------------------
// K1: A = (2x-1)*mask in [B,H,CW] layout; per-image mask count via atomics.
// ---------------------------------------------------------------------------
__global__ void build_kernel(const float* __restrict__ x,
                             const int* __restrict__ mask) {
    int idx = blockIdx.x * 256 + threadIdx.x;
    int b   = idx / (HH * CW);
    int rem = idx - b * (HH * CW);
    int h   = rem / CW;
    int cw  = rem - h * CW;
    int c   = cw / WW;
    int w   = cw - c * WW;

    int m = mask[idx];
    float xv = x[((b * CC + c) * HH + h) * WW + w];
    g_A[idx] = m ? (2.0f * xv - 1.0f) : 0.0f;

    int s = m;
    #pragma unroll
    for (int o = 16; o; o >>= 1) s += __shfl_xor_sync(0xffffffffu, s, o);
    __shared__ int ss[8];
    int warp = threadIdx.x >> 5, lane = threadIdx.x & 31;
    if (lane == 0) ss[warp] = s;
    __syncthreads();
    if (threadIdx.x == 0) {
        int t = 0;
        #pragma unroll
        for (int i = 0; i < 8; i++) t += ss[i];
        atomicAdd(&g_cnt[b], t);
    }
}

// ---------------------------------------------------------------------------
// K2: G = A A^T per image. grid (7,7,BB), block (16,16), 2x2 micro-tile.
// ---------------------------------------------------------------------------
__global__ void gram_kernel() {
    __shared__ float As[32][33];
    __shared__ float Bs[32][33];
    int b  = blockIdx.z;
    int i0 = blockIdx.y * 32, j0 = blockIdx.x * 32;
    const float* Ab = g_A + (size_t)b * HH * CW;
    int tx = threadIdx.x, ty = threadIdx.y;
    int t = ty * 16 + tx;

    float a00 = 0.f, a01 = 0.f, a10 = 0.f, a11 = 0.f;
    for (int k0 = 0; k0 < CW; k0 += 32) {
        #pragma unroll
        for (int q = 0; q < 4; q++) {
            int e = t + q * 256;
            int rr = e >> 5, kk = e & 31;
            As[rr][kk] = Ab[(i0 + rr) * CW + k0 + kk];
            Bs[rr][kk] = Ab[(j0 + rr) * CW + k0 + kk];
        }
        __syncthreads();
        #pragma unroll
        for (int kk = 0; kk < 32; kk++) {
            float x0 = As[2 * ty][kk], x1 = As[2 * ty + 1][kk];
            float y0 = Bs[2 * tx][kk], y1 = Bs[2 * tx + 1][kk];
            a00 += x0 * y0; a01 += x0 * y1;
            a10 += x1 * y0; a11 += x1 * y1;
        }
        __syncthreads();
    }
    float* Gb = g_G + (size_t)b * NN * NN;
    Gb[(i0 + 2 * ty    ) * NN + j0 + 2 * tx    ] = a00;
    Gb[(i0 + 2 * ty    ) * NN + j0 + 2 * tx + 1] = a01;
    Gb[(i0 + 2 * ty + 1) * NN + j0 + 2 * tx    ] = a10;
    Gb[(i0 + 2 * ty + 1) * NN + j0 + 2 * tx + 1] = a11;
}

// ---------------------------------------------------------------------------
// K3: one-sided Jacobi over 2-column blocks (traffic-amortized).
// 448 threads = 56 groups of 8 lanes. Tournament over 112 blocks, 111
// rounds/sweep, group g handles block-pair g. Each group loads 4 columns
// into registers (28 float4/lane), processes all 6 column pairs among them
// sequentially (dot recomputed from registers before each rotation), then
// stores the 4 columns. Crossbar traffic per sweep halves vs pairwise.
// Incremental norms; relative skip threshold; early exit on clean sweep.
// ---------------------------------------------------------------------------
#define ROTPAIR(X, Y)                                                        \
    {                                                                        \
        float pp = 0.f;                                                      \
        _Pragma("unroll")                                                    \
        for (int m = 0; m < 7; m++) {                                        \
            float4 a = pc[X][m], u = pc[Y][m];                               \
            pp += a.x * u.x + a.y * u.y + a.z * u.z + a.w * u.w;             \
        }                                                                    \
        pp += __shfl_xor_sync(0xffffffffu, pp, 4);                           \
        pp += __shfl_xor_sync(0xffffffffu, pp, 2);                           \
        pp += __shfl_xor_sync(0xffffffffu, pp, 1);                           \
        float qi = q[X], qj = q[Y];                                          \
        if (pp * pp > THR * qi * qj) {                                       \
            any = 1;                                                         \
            float tau = (qj - qi) / (2.0f * pp);                             \
            float tt = 1.0f / (fabsf(tau) + sqrtf(1.0f + tau * tau));        \
            if (tau < 0.f) tt = -tt;                                         \
            float c = rsqrtf(1.0f + tt * tt);                                \
            float s = c * tt;                                                \
            _Pragma("unroll")                                                \
            for (int m = 0; m < 7; m++) {                                    \
                float4 a = pc[X][m], u = pc[Y][m];                           \
                float4 ni, nj;                                               \
                ni.x = c * a.x - s * u.x;  nj.x = s * a.x + c * u.x;         \
                ni.y = c * a.y - s * u.y;  nj.y = s * a.y + c * u.y;         \
                ni.z = c * a.z - s * u.z;  nj.z = s * a.z + c * u.z;         \
                ni.w = c * a.w - s * u.w;  nj.w = s * a.w + c * u.w;         \
                pc[X][m] = ni;  pc[Y][m] = nj;                               \
            }                                                                \
            float c2 = c * c, s2 = s * s, cs2 = 2.f * c * s;                 \
            q[X] = c2 * qi - cs2 * pp + s2 * qj;                             \
            q[Y] = s2 * qi + cs2 * pp + c2 * qj;                             \
        }                                                                    \
    }

__global__ void __launch_bounds__(448, 1) jacobi_kernel() {
    extern __shared__ float sm[];
    float* W   = sm;                    // NN*NN, column-major
    float* nrm = sm + NN * NN;          // NN squared norms (maintained)
    int*   rnk = (int*)(nrm + NN);      // NN ranks
    __shared__ int rot_flag;

    int b = blockIdx.x;
    int tid = threadIdx.x, warp = tid >> 5, lane = tid & 31;
    int gl = lane & 7;                  // lane within 8-lane group
    int g  = (warp << 2) | (lane >> 3); // block-pair id 0..55
    const float* Gb = g_G + (size_t)b * NN * NN;

    for (int i = tid; i < NN * NN; i += 448) W[i] = Gb[i];
    __syncthreads();

    // initial column squared norms: 16 cols per warp, full-warp reduce
    #pragma unroll
    for (int k = 0; k < 16; k++) {
        int col = warp * 16 + k;
        const float* cc = W + col * NN;
        float s = 0.f;
        #pragma unroll
        for (int m = 0; m < 7; m++) { float v = cc[lane + 32 * m]; s += v * v; }
        #pragma unroll
        for (int o = 16; o; o >>= 1) s += __shfl_xor_sync(0xffffffffu, s, o);
        if (lane == 0) nrm[col] = s;
    }
    __syncthreads();

    for (int sw = 0; sw < NSWEEP; ++sw) {
        if (tid == 0) rot_flag = 0;
        __syncthreads();
        for (int r = 0; r < NB - 1; ++r) {
            // block pair (I, J) for this group (circle tournament over 112)
            int I, J;
            if (g == 0) { I = NB - 1; J = r; }
            else {
                I = r + g; if (I >= NB - 1) I -= (NB - 1);
                J = r - g; if (J < 0)       J += (NB - 1);
            }
            int c0 = 2 * I, c1 = c0 + 1, c2 = 2 * J, c3 = c2 + 1;
            float4* p0 = (float4*)(W + c0 * NN);
            float4* p1 = (float4*)(W + c1 * NN);
            float4* p2 = (float4*)(W + c2 * NN);
            float4* p3 = (float4*)(W + c3 * NN);

            float4 pc[4][7];
            #pragma unroll
            for (int m = 0; m < 7; m++) {
                pc[0][m] = p0[gl + 8 * m];
                pc[1][m] = p1[gl + 8 * m];
                pc[2][m] = p2[gl + 8 * m];
                pc[3][m] = p3[gl + 8 * m];
            }
            float q[4] = { nrm[c0], nrm[c1], nrm[c2], nrm[c3] };
            int any = 0;

            // 6 pairs, sequential Gauss-Seidel within the 4-column block
            ROTPAIR(0, 1)
            ROTPAIR(2, 3)
            ROTPAIR(0, 2)
            ROTPAIR(0, 3)
            ROTPAIR(1, 2)
            ROTPAIR(1, 3)

            if (any) {
                #pragma unroll
                for (int m = 0; m < 7; m++) {
                    p0[gl + 8 * m] = pc[0][m];
                    p1[gl + 8 * m] = pc[1][m];
                    p2[gl + 8 * m] = pc[2][m];
                    p3[gl + 8 * m] = pc[3][m];
                }
                if (gl == 0) {
                    nrm[c0] = q[0]; nrm[c1] = q[1];
                    nrm[c2] = q[2]; nrm[c3] = q[3];
                    rot_flag = 1;
                }
            }
            __syncthreads();
        }
        int done = (rot_flag == 0);
        __syncthreads();        // all reads of flag precede next reset
        if (done) break;
    }

    // rank of each column (0 = smallest norm), deterministic tie-break
    if (tid < NN) {
        float mine = nrm[tid];
        int rk = 0;
        for (int j = 0; j < NN; j++) {
            float o = nrm[j];
            rk += (o < mine) || (o == mine && j < tid);
        }
        rnk[tid] = rk;
    }
    __syncthreads();

    // write normalized tail-45 eigenvectors (rows of Ut^T), coalesced
    for (int t = 0; t < NN; t++) {
        int rk = rnk[t];
        if (rk < TAIL) {
            float inv = rsqrtf(nrm[t]);   // 1/lambda
            for (int rr = tid; rr < NN; rr += 448)
                g_Ut[((size_t)b * TAIL + rk) * NN + rr] = W[t * NN + rr] * inv;
        }
    }
}

// ---------------------------------------------------------------------------
// K4: R = A - Ut (Ut^T A); epilogue: /p_obs, clip, (r+1)/2, scatter to NCHW.
// Two CTAs per image (336 columns each), T in 45 registers/thread.
// ---------------------------------------------------------------------------
__global__ void __launch_bounds__(336, 2) recon_kernel(float* __restrict__ out) {
    __shared__ __align__(16) float sU[TAIL * NN];
    int b = blockIdx.x >> 1, half = blockIdx.x & 1;
    int tid = threadIdx.x;
    int cw  = half * 336 + tid;
    const float* Ub = g_Ut + (size_t)b * TAIL * NN;
    for (int i = tid; i < TAIL * NN; i += 336) sU[i] = Ub[i];
    __syncthreads();

    const float* Ab = g_A + (size_t)b * HH * CW;
    float inv_p = (float)(HH * CW) / (float)g_cnt[b];

    float acc[TAIL];
    #pragma unroll
    for (int t = 0; t < TAIL; t++) acc[t] = 0.f;

    for (int h = 0; h < HH; h += 4) {
        float a0 = Ab[(h + 0) * CW + cw];
        float a1 = Ab[(h + 1) * CW + cw];
        float a2 = Ab[(h + 2) * CW + cw];
        float a3 = Ab[(h + 3) * CW + cw];
        #pragma unroll
        for (int t = 0; t < TAIL; t++) {
            float4 u = *(const float4*)&sU[t * NN + h];
            acc[t] += u.x * a0 + u.y * a1 + u.z * a2 + u.w * a3;
        }
    }

    int c = cw / WW, w = cw - c * WW;
    float* ob = out + (((size_t)b * CC + c) * HH) * WW + w;

    for (int h = 0; h < HH; h += 4) {
        float a0 = Ab[(h + 0) * CW + cw];
        float a1 = Ab[(h + 1) * CW + cw];
        float a2 = Ab[(h + 2) * CW + cw];
        float a3 = Ab[(h + 3) * CW + cw];
        float s0 = 0.f, s1 = 0.f, s2 = 0.f, s3 = 0.f;
        #pragma unroll
        for (int t = 0; t < TAIL; t++) {
            float4 u = *(const float4*)&sU[t * NN + h];
            float tv = acc[t];
            s0 += u.x * tv; s1 += u.y * tv; s2 += u.z * tv; s3 += u.w * tv;
        }
        float r0 = (a0 - s0) * inv_p;
        float r1 = (a1 - s1) * inv_p;
        float r2 = (a2 - s2) * inv_p;
        float r3 = (a3 - s3) * inv_p;
        r0 = fminf(1.f, fmaxf(-1.f, r0));
        r1 = fminf(1.f, fmaxf(-1.f, r1));
        r2 = fminf(1.f, fmaxf(-1.f, r2));
        r3 = fminf(1.f, fmaxf(-1.f, r3));
        ob[(h + 0) * WW] = 0.5f * r0 + 0.5f;
        ob[(h + 1) * WW] = 0.5f * r1 + 0.5f;
        ob[(h + 2) * WW] = 0.5f * r2 + 0.5f;
        ob[(h + 3) * WW] = 0.5f * r3 + 0.5f;
    }
}

// ---------------------------------------------------------------------------
extern "C" void kernel_launch(void* const* d_in, const int* in_sizes, int n_in,
                              void* d_out, int out_size) {
    const float* x    = (const float*)d_in[0];
    const int*   mask = (const int*)d_in[1];
    float*       out  = (float*)d_out;

    const int JAC_SMEM = (NN * NN + NN) * (int)sizeof(float) + NN * (int)sizeof(int);

    void* cntp = nullptr;
    cudaGetSymbolAddress(&cntp, g_cnt);
    cudaMemsetAsync(cntp, 0, BB * sizeof(int));

    cudaFuncSetAttribute(jacobi_kernel,
                         cudaFuncAttributeMaxDynamicSharedMemorySize, JAC_SMEM);

    build_kernel<<<BB * HH * CW / 256, 256>>>(x, mask);
    gram_kernel<<<dim3(7, 7, BB), dim3(16, 16)>>>();
    jacobi_kernel<<<BB, 448, JAC_SMEM>>>();
    recon_kernel<<<2 * BB, 336>>>(out);
}